// round 1
// baseline (speedup 1.0000x reference)
#include <cuda_runtime.h>
#include <cuda_bf16.h>
#include <cstdint>
#include <cstddef>

#define BB   4
#define CC   256
#define NN   4096
#define GG   32
#define CPG  8
#define EPSV 1e-5f

#define TBM 64
#define TBN 64
#define TBK 16

// ---------------- scratch (device globals) ----------------------------------
__device__ float g_WqkT[CC * 512];
__device__ float g_WvT [CC * CC];
__device__ float g_WoT [CC * CC];
__device__ float g_bqk [512];
__device__ float g_hn  [BB * CC * NN];
__device__ float g_qk  [BB * 512 * NN];
__device__ float g_v   [(size_t)BB * NN * CC];
__device__ float g_sT  [(size_t)BB * NN * NN];
__device__ float g_at  [BB * CC * NN];
__device__ float g_mean[BB * GG];
__device__ float g_rstd[BB * GG];
__device__ float g_pm  [BB * 8 * NN];
__device__ float g_pl  [BB * 8 * NN];

// ---------------- weight prep ------------------------------------------------
__global__ void prep_weights(const float* __restrict__ wq, const float* __restrict__ wk,
                             const float* __restrict__ wv, const float* __restrict__ wo,
                             const float* __restrict__ bq, const float* __restrict__ bk)
{
    int i = blockIdx.x * blockDim.x + threadIdx.x;
    if (i < CC * 1024) {
        int c = i >> 10;
        int j = i & 1023;
        if (j < 256)       g_WqkT[c * 512 + j]        = wq[j * CC + c];
        else if (j < 512)  g_WqkT[c * 512 + j]        = wk[(j - 256) * CC + c];
        else if (j < 768)  g_WvT [c * CC + (j - 512)] = wv[(j - 512) * CC + c];
        else               g_WoT [c * CC + (j - 768)] = wo[(j - 768) * CC + c];
    } else {
        int j = i - CC * 1024;
        if (j < 512) g_bqk[j] = (j < 256) ? bq[j] : bk[j - 256];
    }
}

// ---------------- groupnorm --------------------------------------------------
__global__ void gn_stats(const float* __restrict__ x)
{
    int bg = blockIdx.x;
    const float* xs = x + (size_t)bg * (CPG * NN);
    float s = 0.f, s2 = 0.f;
    for (int i = threadIdx.x; i < CPG * NN; i += 256) {
        float v = xs[i];
        s += v; s2 += v * v;
    }
    __shared__ float rs[512];
    rs[threadIdx.x] = s; rs[256 + threadIdx.x] = s2;
    __syncthreads();
    for (int off = 128; off > 0; off >>= 1) {
        if (threadIdx.x < off) {
            rs[threadIdx.x]       += rs[threadIdx.x + off];
            rs[256 + threadIdx.x] += rs[256 + threadIdx.x + off];
        }
        __syncthreads();
    }
    if (threadIdx.x == 0) {
        float mean = rs[0] * (1.f / (CPG * NN));
        float var  = rs[256] * (1.f / (CPG * NN)) - mean * mean;
        g_mean[bg] = mean;
        g_rstd[bg] = rsqrtf(var + EPSV);
    }
}

__global__ void gn_apply(const float* __restrict__ x,
                         const float* __restrict__ gamma, const float* __restrict__ beta)
{
    int i = blockIdx.x * blockDim.x + threadIdx.x;
    size_t e = (size_t)i * 4;
    int c  = (int)((e >> 12) & 255);
    int bg = (int)(e >> 15);
    float mean = g_mean[bg], rstd = g_rstd[bg];
    float ga = gamma[c] * rstd;
    float be = beta[c] - mean * ga;
    float4 xv = *(const float4*)(x + e);
    float4 o;
    o.x = xv.x * ga + be; o.y = xv.y * ga + be;
    o.z = xv.z * ga + be; o.w = xv.w * ga + be;
    *(float4*)(g_hn + e) = o;
}

// ---------------- TN SGEMM ---------------------------------------------------
// C[m][n] = alpha * sum_k A[k][m] * B[k][n]  (+bias_row[m] +bias_col[n] +residual)
__global__ void __launch_bounds__(256)
tn_gemm(const float* __restrict__ A, const float* __restrict__ B, float* __restrict__ C,
        int M, int N, int K,
        size_t sA, size_t sB, size_t sC,
        float alpha,
        const float* __restrict__ bias_row, const float* __restrict__ bias_col,
        const float* __restrict__ residual)
{
    int bz = blockIdx.z;
    A += (size_t)bz * sA;
    B += (size_t)bz * sB;
    C += (size_t)bz * sC;
    if (residual) residual += (size_t)bz * sC;

    int m0 = blockIdx.y * TBM;
    int n0 = blockIdx.x * TBN;

    __shared__ float As[TBK][TBM];
    __shared__ float Bs[TBK][TBN];

    int tid = threadIdx.x;
    int tx = tid & 15, ty = tid >> 4;
    int lr = tid >> 4;
    int lc = (tid & 15) * 4;

    const float* Aptr = A + (size_t)lr * M + m0 + lc;
    const float* Bptr = B + (size_t)lr * N + n0 + lc;

    float acc[4][4] = {};
    float4 av = *(const float4*)Aptr;
    float4 bv = *(const float4*)Bptr;

    for (int k0 = 0; k0 < K; k0 += TBK) {
        *(float4*)&As[lr][lc] = av;
        *(float4*)&Bs[lr][lc] = bv;
        __syncthreads();
        if (k0 + TBK < K) {
            av = *(const float4*)(Aptr + (size_t)(k0 + TBK) * M);
            bv = *(const float4*)(Bptr + (size_t)(k0 + TBK) * N);
        }
#pragma unroll
        for (int k = 0; k < TBK; k++) {
            float a[4], b[4];
            *(float4*)a = *(const float4*)&As[k][ty * 4];
            *(float4*)b = *(const float4*)&Bs[k][tx * 4];
#pragma unroll
            for (int ii = 0; ii < 4; ii++)
#pragma unroll
                for (int jj = 0; jj < 4; jj++)
                    acc[ii][jj] += a[ii] * b[jj];
        }
        __syncthreads();
    }

    float br[4], bc[4];
#pragma unroll
    for (int ii = 0; ii < 4; ii++) br[ii] = bias_row ? bias_row[m0 + ty * 4 + ii] : 0.f;
#pragma unroll
    for (int jj = 0; jj < 4; jj++) bc[jj] = bias_col ? bias_col[n0 + tx * 4 + jj] : 0.f;

#pragma unroll
    for (int ii = 0; ii < 4; ii++) {
        size_t row = (size_t)(m0 + ty * 4 + ii);
        float4 o;
        o.x = acc[ii][0] * alpha + br[ii] + bc[0];
        o.y = acc[ii][1] * alpha + br[ii] + bc[1];
        o.z = acc[ii][2] * alpha + br[ii] + bc[2];
        o.w = acc[ii][3] * alpha + br[ii] + bc[3];
        if (residual) {
            float4 rv = *(const float4*)(residual + row * N + n0 + tx * 4);
            o.x += rv.x; o.y += rv.y; o.z += rv.z; o.w += rv.w;
        }
        *(float4*)(C + row * N + n0 + tx * 4) = o;
    }
}

// ---------------- column softmax on sT (softmax over slow dim) ---------------
__global__ void softmax_pass1()
{
    int b = blockIdx.z, rc = blockIdx.y, cb = blockIdx.x;
    int col = cb * 256 + threadIdx.x;
    const float* S = g_sT + (size_t)b * NN * NN + (size_t)rc * 512 * NN + col;
    float m = -1e30f, l = 0.f;
#pragma unroll 4
    for (int r = 0; r < 512; r++) {
        float v = S[(size_t)r * NN];
        if (v > m) { l = l * __expf(m - v) + 1.f; m = v; }
        else       { l += __expf(v - m); }
    }
    g_pm[((size_t)b * 8 + rc) * NN + col] = m;
    g_pl[((size_t)b * 8 + rc) * NN + col] = l;
}

__global__ void softmax_pass2()
{
    int b = blockIdx.z, rc = blockIdx.y, cb = blockIdx.x;
    int col = cb * 256 + threadIdx.x;
    float M = -1e30f;
#pragma unroll
    for (int c = 0; c < 8; c++) M = fmaxf(M, g_pm[((size_t)b * 8 + c) * NN + col]);
    float L = 0.f;
#pragma unroll
    for (int c = 0; c < 8; c++)
        L += g_pl[((size_t)b * 8 + c) * NN + col] * __expf(g_pm[((size_t)b * 8 + c) * NN + col] - M);
    float invL = 1.f / L;
    float* S = g_sT + (size_t)b * NN * NN + (size_t)rc * 512 * NN + col;
#pragma unroll 4
    for (int r = 0; r < 512; r++) {
        size_t off = (size_t)r * NN;
        S[off] = __expf(S[off] - M) * invL;
    }
}

// ---------------- launch -----------------------------------------------------
extern "C" void kernel_launch(void* const* d_in, const int* in_sizes, int n_in,
                              void* d_out, int out_size)
{
    const float* x     = (const float*)d_in[0];
    const float* gamma = (const float*)d_in[1];
    const float* beta  = (const float*)d_in[2];
    const float* wq    = (const float*)d_in[3];
    const float* bq    = (const float*)d_in[4];
    const float* wk    = (const float*)d_in[5];
    const float* bk    = (const float*)d_in[6];
    const float* wv    = (const float*)d_in[7];
    const float* bv    = (const float*)d_in[8];
    const float* wo    = (const float*)d_in[9];
    const float* bo    = (const float*)d_in[10];
    float* out = (float*)d_out;

    float *WqkT, *WvT, *WoT, *bqk, *hn, *qk, *v, *sT, *at;
    cudaGetSymbolAddress((void**)&WqkT, g_WqkT);
    cudaGetSymbolAddress((void**)&WvT,  g_WvT);
    cudaGetSymbolAddress((void**)&WoT,  g_WoT);
    cudaGetSymbolAddress((void**)&bqk,  g_bqk);
    cudaGetSymbolAddress((void**)&hn,   g_hn);
    cudaGetSymbolAddress((void**)&qk,   g_qk);
    cudaGetSymbolAddress((void**)&v,    g_v);
    cudaGetSymbolAddress((void**)&sT,   g_sT);
    cudaGetSymbolAddress((void**)&at,   g_at);

    prep_weights<<<(CC * 1024 + 512 + 255) / 256, 256>>>(wq, wk, wv, wo, bq, bk);
    gn_stats<<<BB * GG, 256>>>(x);
    gn_apply<<<(BB * CC * NN / 4) / 256, 256>>>(x, gamma, beta);

    // q,k in [d][n]:  C = WqkT^T(kmaj) x hn(kmaj), bias over rows
    tn_gemm<<<dim3(NN / TBN, 512 / TBM, BB), 256>>>(
        WqkT, hn, qk, 512, NN, CC,
        0, (size_t)CC * NN, (size_t)512 * NN,
        1.f, bqk, nullptr, nullptr);

    // v in [n][d]:  bias over cols
    tn_gemm<<<dim3(CC / TBN, NN / TBM, BB), 256>>>(
        hn, WvT, v, NN, CC, CC,
        (size_t)CC * NN, 0, (size_t)NN * CC,
        1.f, nullptr, bv, nullptr);

    // sT[nk][nq] = (1/16) * k.q
    tn_gemm<<<dim3(NN / TBN, NN / TBM, BB), 256>>>(
        qk + (size_t)CC * NN, qk, sT, NN, NN, CC,
        (size_t)512 * NN, (size_t)512 * NN, (size_t)NN * NN,
        0.0625f, nullptr, nullptr, nullptr);

    softmax_pass1<<<dim3(NN / 256, 8, BB), 256>>>();
    softmax_pass2<<<dim3(NN / 256, 8, BB), 256>>>();

    // attnT[c][nq] = sum_m v[m][c] * P[m][nq]
    tn_gemm<<<dim3(NN / TBN, CC / TBM, BB), 256>>>(
        v, sT, at, CC, NN, NN,
        (size_t)NN * CC, (size_t)NN * NN, (size_t)CC * NN,
        1.f, nullptr, nullptr, nullptr);

    // out[d][n] = WoT^T x attnT + bo[d] + x   (written straight into d_out)
    tn_gemm<<<dim3(NN / TBN, CC / TBM, BB), 256>>>(
        WoT, at, out, CC, NN, CC,
        0, (size_t)CC * NN, (size_t)CC * NN,
        1.f, bo, nullptr, x);
}

// round 2
// speedup vs baseline: 2.4762x; 2.4762x over previous
#include <cuda_runtime.h>
#include <cuda_bf16.h>
#include <cstdint>
#include <cstddef>

#define BB   4
#define CC   256
#define NN   4096
#define GG   32
#define CPG  8
#define EPSV 1e-5f

#define TBM 128
#define TBN 128
#define TBK 16
#define PAD 8          // smem row stride = TBM+8 = 136 -> conflict-free frag LDS

// ---------------- scratch (device globals) ----------------------------------
__device__ float g_WqkT[CC * 512];
__device__ float g_WvT [CC * CC];
__device__ float g_WoT [CC * CC];
__device__ float g_bqk [512];
__device__ float g_hn  [BB * CC * NN];
__device__ float g_qk  [BB * 512 * NN];
__device__ float g_v   [(size_t)BB * NN * CC];
__device__ float g_sT  [(size_t)BB * NN * NN];
__device__ float g_at  [BB * CC * NN];
__device__ float g_mean[BB * GG];
__device__ float g_rstd[BB * GG];
__device__ float g_pm  [BB * 8 * NN];
__device__ float g_pl  [BB * 8 * NN];

// ---------------- helpers ----------------------------------------------------
__device__ __forceinline__ uint32_t f2tf(float f) {
    uint32_t u;
    asm("cvt.rna.tf32.f32 %0, %1;" : "=r"(u) : "f"(f));
    return u;
}

__device__ __forceinline__ void mma_tf32(float& c0, float& c1, float& c2, float& c3,
                                         uint32_t a0, uint32_t a1, uint32_t a2, uint32_t a3,
                                         uint32_t b0, uint32_t b1)
{
    asm volatile(
        "mma.sync.aligned.m16n8k8.row.col.f32.tf32.tf32.f32 "
        "{%0,%1,%2,%3},{%4,%5,%6,%7},{%8,%9},{%0,%1,%2,%3};\n"
        : "+f"(c0), "+f"(c1), "+f"(c2), "+f"(c3)
        : "r"(a0), "r"(a1), "r"(a2), "r"(a3), "r"(b0), "r"(b1));
}

// ---------------- weight prep ------------------------------------------------
__global__ void prep_weights(const float* __restrict__ wq, const float* __restrict__ wk,
                             const float* __restrict__ wv, const float* __restrict__ wo,
                             const float* __restrict__ bq, const float* __restrict__ bk)
{
    int i = blockIdx.x * blockDim.x + threadIdx.x;
    if (i < CC * 1024) {
        int c = i >> 10;
        int j = i & 1023;
        if (j < 256)       g_WqkT[c * 512 + j]        = wq[j * CC + c];
        else if (j < 512)  g_WqkT[c * 512 + j]        = wk[(j - 256) * CC + c];
        else if (j < 768)  g_WvT [c * CC + (j - 512)] = wv[(j - 512) * CC + c];
        else               g_WoT [c * CC + (j - 768)] = wo[(j - 768) * CC + c];
    } else {
        int j = i - CC * 1024;
        if (j < 512) g_bqk[j] = (j < 256) ? bq[j] : bk[j - 256];
    }
}

// ---------------- groupnorm --------------------------------------------------
__global__ void gn_stats(const float* __restrict__ x)
{
    int bg = blockIdx.x;
    const float* xs = x + (size_t)bg * (CPG * NN);
    float s = 0.f, s2 = 0.f;
    for (int i = threadIdx.x; i < CPG * NN; i += 256) {
        float v = xs[i];
        s += v; s2 += v * v;
    }
    __shared__ float rs[512];
    rs[threadIdx.x] = s; rs[256 + threadIdx.x] = s2;
    __syncthreads();
    for (int off = 128; off > 0; off >>= 1) {
        if (threadIdx.x < off) {
            rs[threadIdx.x]       += rs[threadIdx.x + off];
            rs[256 + threadIdx.x] += rs[256 + threadIdx.x + off];
        }
        __syncthreads();
    }
    if (threadIdx.x == 0) {
        float mean = rs[0] * (1.f / (CPG * NN));
        float var  = rs[256] * (1.f / (CPG * NN)) - mean * mean;
        g_mean[bg] = mean;
        g_rstd[bg] = rsqrtf(var + EPSV);
    }
}

__global__ void gn_apply(const float* __restrict__ x,
                         const float* __restrict__ gamma, const float* __restrict__ beta)
{
    int i = blockIdx.x * blockDim.x + threadIdx.x;
    size_t e = (size_t)i * 4;
    int c  = (int)((e >> 12) & 255);
    int bg = (int)(e >> 15);
    float mean = g_mean[bg], rstd = g_rstd[bg];
    float ga = gamma[c] * rstd;
    float be = beta[c] - mean * ga;
    float4 xv = *(const float4*)(x + e);
    float4 o;
    o.x = xv.x * ga + be; o.y = xv.y * ga + be;
    o.z = xv.z * ga + be; o.w = xv.w * ga + be;
    *(float4*)(g_hn + e) = o;
}

// ---------------- TF32 tensor-core TN GEMM -----------------------------------
// C[m][n] = alpha * sum_k A[k][m] * B[k][n]  (+bias_row[m] +bias_col[n] +residual)
// A, B are K-major in global. 128x128x16 block tile, 256 threads,
// warp grid 2(m) x 4(n), each warp: 64x32 via m16n8k8 tf32 MMA.
__global__ void __launch_bounds__(256)
tn_gemm_tc(const float* __restrict__ A, const float* __restrict__ B, float* __restrict__ C,
           int M, int N, int K,
           size_t sA, size_t sB, size_t sC,
           float alpha,
           const float* __restrict__ bias_row, const float* __restrict__ bias_col,
           const float* __restrict__ residual)
{
    int bz = blockIdx.z;
    A += (size_t)bz * sA;
    B += (size_t)bz * sB;
    C += (size_t)bz * sC;
    if (residual) residual += (size_t)bz * sC;

    const int m0 = blockIdx.y * TBM;
    const int n0 = blockIdx.x * TBN;

    __shared__ uint32_t As[TBK][TBM + PAD];
    __shared__ uint32_t Bs[TBK][TBN + PAD];

    const int tid  = threadIdx.x;
    const int lane = tid & 31;
    const int wid  = tid >> 5;
    const int wm   = wid >> 2;        // 0..1 -> m offset wm*64
    const int wn   = wid & 3;         // 0..3 -> n offset wn*32
    const int g    = lane >> 2;       // 0..7
    const int th4  = lane & 3;        // 0..3

    // global copy indices: 16 rows x 128 cols per tile; 2 float4 per thread
    const int cr = tid >> 5;          // 0..7 (and cr+8)
    const int cc = (tid & 31) * 4;    // 0..124

    const float* Ap = A + (size_t)cr * M + m0 + cc;
    const float* Bp = B + (size_t)cr * N + n0 + cc;
    const size_t a8 = (size_t)8 * M;
    const size_t b8 = (size_t)8 * N;

    float4 av0 = *(const float4*)Ap;
    float4 av1 = *(const float4*)(Ap + a8);
    float4 bv0 = *(const float4*)Bp;
    float4 bv1 = *(const float4*)(Bp + b8);

    float acc[4][4][4];
#pragma unroll
    for (int i = 0; i < 4; i++)
#pragma unroll
        for (int j = 0; j < 4; j++)
#pragma unroll
            for (int r = 0; r < 4; r++) acc[i][j][r] = 0.f;

    for (int k0 = 0; k0 < K; k0 += TBK) {
        As[cr][cc]     = f2tf(av0.x); As[cr][cc + 1]     = f2tf(av0.y);
        As[cr][cc + 2] = f2tf(av0.z); As[cr][cc + 3]     = f2tf(av0.w);
        As[cr + 8][cc]     = f2tf(av1.x); As[cr + 8][cc + 1] = f2tf(av1.y);
        As[cr + 8][cc + 2] = f2tf(av1.z); As[cr + 8][cc + 3] = f2tf(av1.w);
        Bs[cr][cc]     = f2tf(bv0.x); Bs[cr][cc + 1]     = f2tf(bv0.y);
        Bs[cr][cc + 2] = f2tf(bv0.z); Bs[cr][cc + 3]     = f2tf(bv0.w);
        Bs[cr + 8][cc]     = f2tf(bv1.x); Bs[cr + 8][cc + 1] = f2tf(bv1.y);
        Bs[cr + 8][cc + 2] = f2tf(bv1.z); Bs[cr + 8][cc + 3] = f2tf(bv1.w);
        __syncthreads();

        if (k0 + TBK < K) {
            const float* Apn = Ap + (size_t)(k0 + TBK) * M;
            const float* Bpn = Bp + (size_t)(k0 + TBK) * N;
            av0 = *(const float4*)Apn;
            av1 = *(const float4*)(Apn + a8);
            bv0 = *(const float4*)Bpn;
            bv1 = *(const float4*)(Bpn + b8);
        }

#pragma unroll
        for (int kk = 0; kk < TBK; kk += 8) {
            uint32_t af[4][4], bf[4][2];
#pragma unroll
            for (int mt = 0; mt < 4; mt++) {
                int r0 = wm * 64 + mt * 16 + g;
                af[mt][0] = As[kk + th4][r0];
                af[mt][1] = As[kk + th4][r0 + 8];
                af[mt][2] = As[kk + th4 + 4][r0];
                af[mt][3] = As[kk + th4 + 4][r0 + 8];
            }
#pragma unroll
            for (int nt = 0; nt < 4; nt++) {
                int cb = wn * 32 + nt * 8 + g;
                bf[nt][0] = Bs[kk + th4][cb];
                bf[nt][1] = Bs[kk + th4 + 4][cb];
            }
#pragma unroll
            for (int mt = 0; mt < 4; mt++)
#pragma unroll
                for (int nt = 0; nt < 4; nt++)
                    mma_tf32(acc[mt][nt][0], acc[mt][nt][1], acc[mt][nt][2], acc[mt][nt][3],
                             af[mt][0], af[mt][1], af[mt][2], af[mt][3],
                             bf[nt][0], bf[nt][1]);
        }
        __syncthreads();
    }

    // epilogue: c0,c1 at (row, col..col+1); c2,c3 at (row+8, col..col+1)
#pragma unroll
    for (int mt = 0; mt < 4; mt++) {
        int row = m0 + wm * 64 + mt * 16 + g;
#pragma unroll
        for (int nt = 0; nt < 4; nt++) {
            int col = n0 + wn * 32 + nt * 8 + 2 * th4;
            float bc0 = bias_col ? bias_col[col]     : 0.f;
            float bc1 = bias_col ? bias_col[col + 1] : 0.f;
#pragma unroll
            for (int h = 0; h < 2; h++) {
                int r = row + h * 8;
                float br = bias_row ? bias_row[r] : 0.f;
                float2 o;
                o.x = acc[mt][nt][2 * h]     * alpha + br + bc0;
                o.y = acc[mt][nt][2 * h + 1] * alpha + br + bc1;
                if (residual) {
                    float2 rv = *(const float2*)(residual + (size_t)r * N + col);
                    o.x += rv.x; o.y += rv.y;
                }
                *(float2*)(C + (size_t)r * N + col) = o;
            }
        }
    }
}

// ---------------- column softmax on sT (softmax over slow dim) ---------------
__global__ void softmax_pass1()
{
    int b = blockIdx.z, rc = blockIdx.y, cb = blockIdx.x;
    int col = cb * 256 + threadIdx.x;
    const float* S = g_sT + (size_t)b * NN * NN + (size_t)rc * 512 * NN + col;
    float m = -1e30f, l = 0.f;
#pragma unroll 4
    for (int r = 0; r < 512; r++) {
        float v = S[(size_t)r * NN];
        if (v > m) { l = l * __expf(m - v) + 1.f; m = v; }
        else       { l += __expf(v - m); }
    }
    g_pm[((size_t)b * 8 + rc) * NN + col] = m;
    g_pl[((size_t)b * 8 + rc) * NN + col] = l;
}

__global__ void softmax_pass2()
{
    int b = blockIdx.z, rc = blockIdx.y, cb = blockIdx.x;
    int col = cb * 256 + threadIdx.x;
    float M = -1e30f;
#pragma unroll
    for (int c = 0; c < 8; c++) M = fmaxf(M, g_pm[((size_t)b * 8 + c) * NN + col]);
    float L = 0.f;
#pragma unroll
    for (int c = 0; c < 8; c++)
        L += g_pl[((size_t)b * 8 + c) * NN + col] * __expf(g_pm[((size_t)b * 8 + c) * NN + col] - M);
    float invL = 1.f / L;
    float* S = g_sT + (size_t)b * NN * NN + (size_t)rc * 512 * NN + col;
#pragma unroll 4
    for (int r = 0; r < 512; r++) {
        size_t off = (size_t)r * NN;
        S[off] = __expf(S[off] - M) * invL;
    }
}

// ---------------- launch -----------------------------------------------------
extern "C" void kernel_launch(void* const* d_in, const int* in_sizes, int n_in,
                              void* d_out, int out_size)
{
    const float* x     = (const float*)d_in[0];
    const float* gamma = (const float*)d_in[1];
    const float* beta  = (const float*)d_in[2];
    const float* wq    = (const float*)d_in[3];
    const float* bq    = (const float*)d_in[4];
    const float* wk    = (const float*)d_in[5];
    const float* bk    = (const float*)d_in[6];
    const float* wv    = (const float*)d_in[7];
    const float* bv    = (const float*)d_in[8];
    const float* wo    = (const float*)d_in[9];
    const float* bo    = (const float*)d_in[10];
    float* out = (float*)d_out;

    float *WqkT, *WvT, *WoT, *bqk, *hn, *qk, *v, *sT, *at;
    cudaGetSymbolAddress((void**)&WqkT, g_WqkT);
    cudaGetSymbolAddress((void**)&WvT,  g_WvT);
    cudaGetSymbolAddress((void**)&WoT,  g_WoT);
    cudaGetSymbolAddress((void**)&bqk,  g_bqk);
    cudaGetSymbolAddress((void**)&hn,   g_hn);
    cudaGetSymbolAddress((void**)&qk,   g_qk);
    cudaGetSymbolAddress((void**)&v,    g_v);
    cudaGetSymbolAddress((void**)&sT,   g_sT);
    cudaGetSymbolAddress((void**)&at,   g_at);

    prep_weights<<<(CC * 1024 + 512 + 255) / 256, 256>>>(wq, wk, wv, wo, bq, bk);
    gn_stats<<<BB * GG, 256>>>(x);
    gn_apply<<<(BB * CC * NN / 4) / 256, 256>>>(x, gamma, beta);

    // q,k in [d][n]:  bias over rows
    tn_gemm_tc<<<dim3(NN / TBN, 512 / TBM, BB), 256>>>(
        WqkT, hn, qk, 512, NN, CC,
        0, (size_t)CC * NN, (size_t)512 * NN,
        1.f, bqk, nullptr, nullptr);

    // v in [n][d]:  bias over cols
    tn_gemm_tc<<<dim3(CC / TBN, NN / TBM, BB), 256>>>(
        hn, WvT, v, NN, CC, CC,
        (size_t)CC * NN, 0, (size_t)NN * CC,
        1.f, nullptr, bv, nullptr);

    // sT[nk][nq] = (1/16) * k.q
    tn_gemm_tc<<<dim3(NN / TBN, NN / TBM, BB), 256>>>(
        qk + (size_t)CC * NN, qk, sT, NN, NN, CC,
        (size_t)512 * NN, (size_t)512 * NN, (size_t)NN * NN,
        0.0625f, nullptr, nullptr, nullptr);

    softmax_pass1<<<dim3(NN / 256, 8, BB), 256>>>();
    softmax_pass2<<<dim3(NN / 256, 8, BB), 256>>>();

    // attnT[c][nq] = sum_m v[m][c] * P[m][nq]
    tn_gemm_tc<<<dim3(NN / TBN, CC / TBM, BB), 256>>>(
        v, sT, at, CC, NN, NN,
        (size_t)NN * CC, (size_t)NN * NN, (size_t)CC * NN,
        1.f, nullptr, nullptr, nullptr);

    // out[d][n] = WoT^T x attnT + bo[d] + x   (written straight into d_out)
    tn_gemm_tc<<<dim3(NN / TBN, CC / TBM, BB), 256>>>(
        WoT, at, out, CC, NN, CC,
        0, (size_t)CC * NN, (size_t)CC * NN,
        1.f, bo, nullptr, x);
}

// round 3
// speedup vs baseline: 2.7351x; 1.1045x over previous
#include <cuda_runtime.h>
#include <cuda_bf16.h>
#include <cstdint>
#include <cstddef>

#define BB   4
#define CC   256
#define NN   4096
#define GG   32
#define CPG  8
#define EPSV 1e-5f

#define TBM 128
#define TBN 128
#define TBK 16
#define PAD 8          // smem row stride = 136 words -> conflict-free frag LDS

// ---------------- scratch (device globals) ----------------------------------
__device__ float g_WqkT[CC * 512];
__device__ float g_WvT [CC * CC];
__device__ float g_WoT [CC * CC];
__device__ float g_bqk [512];
__device__ float g_hn  [BB * CC * NN];
__device__ float g_qk  [BB * 512 * NN];
__device__ float g_v   [(size_t)BB * NN * CC];
__device__ float g_sT  [(size_t)BB * NN * NN];
__device__ float g_at  [BB * CC * NN];
__device__ float g_mean[BB * GG];
__device__ float g_rstd[BB * GG];
__device__ float g_pm  [BB * 8 * NN];
__device__ float g_pl  [BB * 8 * NN];

// ---------------- helpers ----------------------------------------------------
__device__ __forceinline__ void mma_tf32(float& c0, float& c1, float& c2, float& c3,
                                         uint32_t a0, uint32_t a1, uint32_t a2, uint32_t a3,
                                         uint32_t b0, uint32_t b1)
{
    asm volatile(
        "mma.sync.aligned.m16n8k8.row.col.f32.tf32.tf32.f32 "
        "{%0,%1,%2,%3},{%4,%5,%6,%7},{%8,%9},{%0,%1,%2,%3};\n"
        : "+f"(c0), "+f"(c1), "+f"(c2), "+f"(c3)
        : "r"(a0), "r"(a1), "r"(a2), "r"(a3), "r"(b0), "r"(b1));
}

__device__ __forceinline__ void cp_async16(void* smem_dst, const void* gptr)
{
    uint32_t s = (uint32_t)__cvta_generic_to_shared(smem_dst);
    asm volatile("cp.async.cg.shared.global [%0], [%1], 16;\n" :: "r"(s), "l"(gptr));
}
__device__ __forceinline__ void cp_commit() { asm volatile("cp.async.commit_group;\n"); }
template <int Nw>
__device__ __forceinline__ void cp_wait() { asm volatile("cp.async.wait_group %0;\n" :: "n"(Nw)); }

// ---------------- weight prep ------------------------------------------------
__global__ void prep_weights(const float* __restrict__ wq, const float* __restrict__ wk,
                             const float* __restrict__ wv, const float* __restrict__ wo,
                             const float* __restrict__ bq, const float* __restrict__ bk)
{
    int i = blockIdx.x * blockDim.x + threadIdx.x;
    if (i < CC * 1024) {
        int c = i >> 10;
        int j = i & 1023;
        if (j < 256)       g_WqkT[c * 512 + j]        = wq[j * CC + c];
        else if (j < 512)  g_WqkT[c * 512 + j]        = wk[(j - 256) * CC + c];
        else if (j < 768)  g_WvT [c * CC + (j - 512)] = wv[(j - 512) * CC + c];
        else               g_WoT [c * CC + (j - 768)] = wo[(j - 768) * CC + c];
    } else {
        int j = i - CC * 1024;
        if (j < 512) g_bqk[j] = (j < 256) ? bq[j] : bk[j - 256];
    }
}

// ---------------- groupnorm --------------------------------------------------
__global__ void gn_stats(const float* __restrict__ x)
{
    int bg = blockIdx.x;
    const float* xs = x + (size_t)bg * (CPG * NN);
    float s = 0.f, s2 = 0.f;
    for (int i = threadIdx.x; i < CPG * NN; i += 256) {
        float v = xs[i];
        s += v; s2 += v * v;
    }
    __shared__ float rs[512];
    rs[threadIdx.x] = s; rs[256 + threadIdx.x] = s2;
    __syncthreads();
    for (int off = 128; off > 0; off >>= 1) {
        if (threadIdx.x < off) {
            rs[threadIdx.x]       += rs[threadIdx.x + off];
            rs[256 + threadIdx.x] += rs[256 + threadIdx.x + off];
        }
        __syncthreads();
    }
    if (threadIdx.x == 0) {
        float mean = rs[0] * (1.f / (CPG * NN));
        float var  = rs[256] * (1.f / (CPG * NN)) - mean * mean;
        g_mean[bg] = mean;
        g_rstd[bg] = rsqrtf(var + EPSV);
    }
}

__global__ void gn_apply(const float* __restrict__ x,
                         const float* __restrict__ gamma, const float* __restrict__ beta)
{
    int i = blockIdx.x * blockDim.x + threadIdx.x;
    size_t e = (size_t)i * 4;
    int c  = (int)((e >> 12) & 255);
    int bg = (int)(e >> 15);
    float mean = g_mean[bg], rstd = g_rstd[bg];
    float ga = gamma[c] * rstd;
    float be = beta[c] - mean * ga;
    float4 xv = *(const float4*)(x + e);
    float4 o;
    o.x = xv.x * ga + be; o.y = xv.y * ga + be;
    o.z = xv.z * ga + be; o.w = xv.w * ga + be;
    *(float4*)(g_hn + e) = o;
}

// ---------------- TF32 tensor-core TN GEMM, cp.async double-buffered ---------
// C[m][n] = alpha * sum_k A[k][m] * B[k][n]  (+bias_row[m] +bias_col[n] +residual)
__global__ void __launch_bounds__(256)
tn_gemm_tc(const float* __restrict__ A, const float* __restrict__ B, float* __restrict__ C,
           int M, int N, int K,
           size_t sA, size_t sB, size_t sC,
           float alpha,
           const float* __restrict__ bias_row, const float* __restrict__ bias_col,
           const float* __restrict__ residual)
{
    int bz = blockIdx.z;
    A += (size_t)bz * sA;
    B += (size_t)bz * sB;
    C += (size_t)bz * sC;
    if (residual) residual += (size_t)bz * sC;

    const int m0 = blockIdx.y * TBM;
    const int n0 = blockIdx.x * TBN;

    __shared__ uint32_t As[2][TBK][TBM + PAD];
    __shared__ uint32_t Bs[2][TBK][TBN + PAD];

    const int tid  = threadIdx.x;
    const int lane = tid & 31;
    const int wid  = tid >> 5;
    const int wm   = wid >> 2;        // 0..1 -> m offset wm*64
    const int wn   = wid & 3;         // 0..3 -> n offset wn*32
    const int g    = lane >> 2;       // 0..7
    const int th4  = lane & 3;        // 0..3

    // global copy indices: 16 rows x 128 cols per tile; 2 float4 per thread per array
    const int cr = tid >> 5;          // 0..7 (and cr+8)
    const int cc = (tid & 31) * 4;    // 0..124

    const float* Ap = A + (size_t)cr * M + m0 + cc;
    const float* Bp = B + (size_t)cr * N + n0 + cc;
    const size_t a8 = (size_t)8 * M;
    const size_t b8 = (size_t)8 * N;

    float acc[4][4][4];
#pragma unroll
    for (int i = 0; i < 4; i++)
#pragma unroll
        for (int j = 0; j < 4; j++)
#pragma unroll
            for (int r = 0; r < 4; r++) acc[i][j][r] = 0.f;

    // prologue: stage 0
    cp_async16(&As[0][cr][cc],     Ap);
    cp_async16(&As[0][cr + 8][cc], Ap + a8);
    cp_async16(&Bs[0][cr][cc],     Bp);
    cp_async16(&Bs[0][cr + 8][cc], Bp + b8);
    cp_commit();

    int s = 0;
    for (int k0 = 0; k0 < K; k0 += TBK, s ^= 1) {
        if (k0 + TBK < K) {
            const float* Apn = Ap + (size_t)(k0 + TBK) * M;
            const float* Bpn = Bp + (size_t)(k0 + TBK) * N;
            cp_async16(&As[s ^ 1][cr][cc],     Apn);
            cp_async16(&As[s ^ 1][cr + 8][cc], Apn + a8);
            cp_async16(&Bs[s ^ 1][cr][cc],     Bpn);
            cp_async16(&Bs[s ^ 1][cr + 8][cc], Bpn + b8);
            cp_commit();
            cp_wait<1>();
        } else {
            cp_wait<0>();
        }
        __syncthreads();

#pragma unroll
        for (int kk = 0; kk < TBK; kk += 8) {
            uint32_t af[4][4], bf[4][2];
#pragma unroll
            for (int mt = 0; mt < 4; mt++) {
                int r0 = wm * 64 + mt * 16 + g;
                af[mt][0] = As[s][kk + th4][r0];
                af[mt][1] = As[s][kk + th4][r0 + 8];
                af[mt][2] = As[s][kk + th4 + 4][r0];
                af[mt][3] = As[s][kk + th4 + 4][r0 + 8];
            }
#pragma unroll
            for (int nt = 0; nt < 4; nt++) {
                int cb = wn * 32 + nt * 8 + g;
                bf[nt][0] = Bs[s][kk + th4][cb];
                bf[nt][1] = Bs[s][kk + th4 + 4][cb];
            }
#pragma unroll
            for (int mt = 0; mt < 4; mt++)
#pragma unroll
                for (int nt = 0; nt < 4; nt++)
                    mma_tf32(acc[mt][nt][0], acc[mt][nt][1], acc[mt][nt][2], acc[mt][nt][3],
                             af[mt][0], af[mt][1], af[mt][2], af[mt][3],
                             bf[nt][0], bf[nt][1]);
        }
        __syncthreads();
    }

    // epilogue
#pragma unroll
    for (int mt = 0; mt < 4; mt++) {
        int row = m0 + wm * 64 + mt * 16 + g;
#pragma unroll
        for (int nt = 0; nt < 4; nt++) {
            int col = n0 + wn * 32 + nt * 8 + 2 * th4;
            float bc0 = bias_col ? bias_col[col]     : 0.f;
            float bc1 = bias_col ? bias_col[col + 1] : 0.f;
#pragma unroll
            for (int h = 0; h < 2; h++) {
                int r = row + h * 8;
                float br = bias_row ? bias_row[r] : 0.f;
                float2 o;
                o.x = acc[mt][nt][2 * h]     * alpha + br + bc0;
                o.y = acc[mt][nt][2 * h + 1] * alpha + br + bc1;
                if (residual) {
                    float2 rv = *(const float2*)(residual + (size_t)r * N + col);
                    o.x += rv.x; o.y += rv.y;
                }
                *(float2*)(C + (size_t)r * N + col) = o;
            }
        }
    }
}

// ---------------- column softmax on sT (softmax over slow dim) ---------------
__global__ void softmax_pass1()
{
    int b = blockIdx.z, rc = blockIdx.y, cb = blockIdx.x;
    int col = cb * 256 + threadIdx.x;
    const float* S = g_sT + (size_t)b * NN * NN + (size_t)rc * 512 * NN + col;
    float m = -1e30f, l = 0.f;
#pragma unroll 4
    for (int r = 0; r < 512; r++) {
        float v = S[(size_t)r * NN];
        if (v > m) { l = l * __expf(m - v) + 1.f; m = v; }
        else       { l += __expf(v - m); }
    }
    g_pm[((size_t)b * 8 + rc) * NN + col] = m;
    g_pl[((size_t)b * 8 + rc) * NN + col] = l;
}

__global__ void softmax_pass2()
{
    int b = blockIdx.z, rc = blockIdx.y, cb = blockIdx.x;
    int col = cb * 256 + threadIdx.x;
    float M = -1e30f;
#pragma unroll
    for (int c = 0; c < 8; c++) M = fmaxf(M, g_pm[((size_t)b * 8 + c) * NN + col]);
    float L = 0.f;
#pragma unroll
    for (int c = 0; c < 8; c++)
        L += g_pl[((size_t)b * 8 + c) * NN + col] * __expf(g_pm[((size_t)b * 8 + c) * NN + col] - M);
    float invL = 1.f / L;
    float* S = g_sT + (size_t)b * NN * NN + (size_t)rc * 512 * NN + col;
#pragma unroll 4
    for (int r = 0; r < 512; r++) {
        size_t off = (size_t)r * NN;
        S[off] = __expf(S[off] - M) * invL;
    }
}

// ---------------- launch -----------------------------------------------------
extern "C" void kernel_launch(void* const* d_in, const int* in_sizes, int n_in,
                              void* d_out, int out_size)
{
    const float* x     = (const float*)d_in[0];
    const float* gamma = (const float*)d_in[1];
    const float* beta  = (const float*)d_in[2];
    const float* wq    = (const float*)d_in[3];
    const float* bq    = (const float*)d_in[4];
    const float* wk    = (const float*)d_in[5];
    const float* bk    = (const float*)d_in[6];
    const float* wv    = (const float*)d_in[7];
    const float* bv    = (const float*)d_in[8];
    const float* wo    = (const float*)d_in[9];
    const float* bo    = (const float*)d_in[10];
    float* out = (float*)d_out;

    float *WqkT, *WvT, *WoT, *bqk, *hn, *qk, *v, *sT, *at;
    cudaGetSymbolAddress((void**)&WqkT, g_WqkT);
    cudaGetSymbolAddress((void**)&WvT,  g_WvT);
    cudaGetSymbolAddress((void**)&WoT,  g_WoT);
    cudaGetSymbolAddress((void**)&bqk,  g_bqk);
    cudaGetSymbolAddress((void**)&hn,   g_hn);
    cudaGetSymbolAddress((void**)&qk,   g_qk);
    cudaGetSymbolAddress((void**)&v,    g_v);
    cudaGetSymbolAddress((void**)&sT,   g_sT);
    cudaGetSymbolAddress((void**)&at,   g_at);

    prep_weights<<<(CC * 1024 + 512 + 255) / 256, 256>>>(wq, wk, wv, wo, bq, bk);
    gn_stats<<<BB * GG, 256>>>(x);
    gn_apply<<<(BB * CC * NN / 4) / 256, 256>>>(x, gamma, beta);

    // q,k in [d][n]:  bias over rows
    tn_gemm_tc<<<dim3(NN / TBN, 512 / TBM, BB), 256>>>(
        WqkT, hn, qk, 512, NN, CC,
        0, (size_t)CC * NN, (size_t)512 * NN,
        1.f, bqk, nullptr, nullptr);

    // v in [n][d]:  bias over cols
    tn_gemm_tc<<<dim3(CC / TBN, NN / TBM, BB), 256>>>(
        hn, WvT, v, NN, CC, CC,
        (size_t)CC * NN, 0, (size_t)NN * CC,
        1.f, nullptr, bv, nullptr);

    // sT[nk][nq] = (1/16) * k.q
    tn_gemm_tc<<<dim3(NN / TBN, NN / TBM, BB), 256>>>(
        qk + (size_t)CC * NN, qk, sT, NN, NN, CC,
        (size_t)512 * NN, (size_t)512 * NN, (size_t)NN * NN,
        0.0625f, nullptr, nullptr, nullptr);

    softmax_pass1<<<dim3(NN / 256, 8, BB), 256>>>();
    softmax_pass2<<<dim3(NN / 256, 8, BB), 256>>>();

    // attnT[c][nq] = sum_m v[m][c] * P[m][nq]
    tn_gemm_tc<<<dim3(NN / TBN, CC / TBM, BB), 256>>>(
        v, sT, at, CC, NN, NN,
        (size_t)NN * CC, (size_t)NN * NN, (size_t)CC * NN,
        1.f, nullptr, nullptr, nullptr);

    // out[d][n] = WoT^T x attnT + bo[d] + x   (written straight into d_out)
    tn_gemm_tc<<<dim3(NN / TBN, CC / TBM, BB), 256>>>(
        WoT, at, out, CC, NN, CC,
        0, (size_t)CC * NN, (size_t)CC * NN,
        1.f, bo, nullptr, x);
}

// round 4
// speedup vs baseline: 2.7535x; 1.0067x over previous
#include <cuda_runtime.h>
#include <cuda_bf16.h>
#include <cstdint>
#include <cstddef>

#define BB   4
#define CC   256
#define NN   4096
#define GG   32
#define CPG  8
#define EPSV 1e-5f

#define TBM 128
#define TBN 128
#define TBK 16
#define PAD 8
#define STAGES 4

#define SMEM_WORDS_PER_STAGE (TBK * (TBM + PAD) + TBK * (TBN + PAD))
#define SMEM_BYTES (STAGES * SMEM_WORDS_PER_STAGE * 4)

// ---------------- scratch (device globals) ----------------------------------
__device__ float g_WqkT[CC * 512];
__device__ float g_WvT [CC * CC];
__device__ float g_WoT [CC * CC];
__device__ float g_bqk [512];
__device__ float g_hn  [BB * CC * NN];
__device__ float g_qk  [BB * 512 * NN];
__device__ float g_v   [(size_t)BB * NN * CC];
__device__ float g_sT  [(size_t)BB * NN * NN];
__device__ float g_at  [BB * CC * NN];
__device__ float g_mean[BB * GG];
__device__ float g_rstd[BB * GG];
__device__ float g_pm  [BB * 8 * NN];
__device__ float g_pl  [BB * 8 * NN];

// ---------------- helpers ----------------------------------------------------
__device__ __forceinline__ void mma_tf32(float& c0, float& c1, float& c2, float& c3,
                                         uint32_t a0, uint32_t a1, uint32_t a2, uint32_t a3,
                                         uint32_t b0, uint32_t b1)
{
    asm volatile(
        "mma.sync.aligned.m16n8k8.row.col.f32.tf32.tf32.f32 "
        "{%0,%1,%2,%3},{%4,%5,%6,%7},{%8,%9},{%0,%1,%2,%3};\n"
        : "+f"(c0), "+f"(c1), "+f"(c2), "+f"(c3)
        : "r"(a0), "r"(a1), "r"(a2), "r"(a3), "r"(b0), "r"(b1));
}

__device__ __forceinline__ void cp_async16(void* smem_dst, const void* gptr)
{
    uint32_t s = (uint32_t)__cvta_generic_to_shared(smem_dst);
    asm volatile("cp.async.cg.shared.global [%0], [%1], 16;\n" :: "r"(s), "l"(gptr));
}
__device__ __forceinline__ void cp_commit() { asm volatile("cp.async.commit_group;\n"); }
template <int Nw>
__device__ __forceinline__ void cp_wait() { asm volatile("cp.async.wait_group %0;\n" :: "n"(Nw)); }

// ---------------- weight prep ------------------------------------------------
__global__ void prep_weights(const float* __restrict__ wq, const float* __restrict__ wk,
                             const float* __restrict__ wv, const float* __restrict__ wo,
                             const float* __restrict__ bq, const float* __restrict__ bk)
{
    int i = blockIdx.x * blockDim.x + threadIdx.x;
    if (i < CC * 1024) {
        int c = i >> 10;
        int j = i & 1023;
        if (j < 256)       g_WqkT[c * 512 + j]        = wq[j * CC + c];
        else if (j < 512)  g_WqkT[c * 512 + j]        = wk[(j - 256) * CC + c];
        else if (j < 768)  g_WvT [c * CC + (j - 512)] = wv[(j - 512) * CC + c];
        else               g_WoT [c * CC + (j - 768)] = wo[(j - 768) * CC + c];
    } else {
        int j = i - CC * 1024;
        if (j < 512) g_bqk[j] = (j < 256) ? bq[j] : bk[j - 256];
    }
}

// ---------------- groupnorm --------------------------------------------------
__global__ void gn_stats(const float* __restrict__ x)
{
    int bg = blockIdx.x;
    const float* xs = x + (size_t)bg * (CPG * NN);
    float s = 0.f, s2 = 0.f;
    for (int i = threadIdx.x; i < CPG * NN; i += 256) {
        float v = xs[i];
        s += v; s2 += v * v;
    }
    __shared__ float rs[512];
    rs[threadIdx.x] = s; rs[256 + threadIdx.x] = s2;
    __syncthreads();
    for (int off = 128; off > 0; off >>= 1) {
        if (threadIdx.x < off) {
            rs[threadIdx.x]       += rs[threadIdx.x + off];
            rs[256 + threadIdx.x] += rs[256 + threadIdx.x + off];
        }
        __syncthreads();
    }
    if (threadIdx.x == 0) {
        float mean = rs[0] * (1.f / (CPG * NN));
        float var  = rs[256] * (1.f / (CPG * NN)) - mean * mean;
        g_mean[bg] = mean;
        g_rstd[bg] = rsqrtf(var + EPSV);
    }
}

__global__ void gn_apply(const float* __restrict__ x,
                         const float* __restrict__ gamma, const float* __restrict__ beta)
{
    int i = blockIdx.x * blockDim.x + threadIdx.x;
    size_t e = (size_t)i * 4;
    int c  = (int)((e >> 12) & 255);
    int bg = (int)(e >> 15);
    float mean = g_mean[bg], rstd = g_rstd[bg];
    float ga = gamma[c] * rstd;
    float be = beta[c] - mean * ga;
    float4 xv = *(const float4*)(x + e);
    float4 o;
    o.x = xv.x * ga + be; o.y = xv.y * ga + be;
    o.z = xv.z * ga + be; o.w = xv.w * ga + be;
    *(float4*)(g_hn + e) = o;
}

// ---------------- TF32 TC GEMM, 4-stage cp.async multistage ------------------
// C[m][n] = alpha * sum_k A[k][m] * B[k][n]  (+bias_row[m] +bias_col[n] +residual)
__global__ void __launch_bounds__(256)
tn_gemm_tc(const float* __restrict__ A, const float* __restrict__ B, float* __restrict__ C,
           int M, int N, int K,
           size_t sA, size_t sB, size_t sC,
           float alpha,
           const float* __restrict__ bias_row, const float* __restrict__ bias_col,
           const float* __restrict__ residual)
{
    int bz = blockIdx.z;
    A += (size_t)bz * sA;
    B += (size_t)bz * sB;
    C += (size_t)bz * sC;
    if (residual) residual += (size_t)bz * sC;

    const int m0 = blockIdx.y * TBM;
    const int n0 = blockIdx.x * TBN;

    extern __shared__ uint32_t smem[];
    typedef uint32_t AsT[TBK][TBM + PAD];
    typedef uint32_t BsT[TBK][TBN + PAD];
    AsT* As = (AsT*)smem;
    BsT* Bs = (BsT*)(smem + STAGES * TBK * (TBM + PAD));

    const int tid  = threadIdx.x;
    const int lane = tid & 31;
    const int wid  = tid >> 5;
    const int wm   = wid >> 2;
    const int wn   = wid & 3;
    const int g    = lane >> 2;
    const int th4  = lane & 3;

    const int cr = tid >> 5;          // 0..7 (and cr+8)
    const int cc = (tid & 31) * 4;    // 0..124

    const float* Ap = A + (size_t)cr * M + m0 + cc;
    const float* Bp = B + (size_t)cr * N + n0 + cc;
    const size_t a8 = (size_t)8 * M;
    const size_t b8 = (size_t)8 * N;

    float acc[4][4][4];
#pragma unroll
    for (int i = 0; i < 4; i++)
#pragma unroll
        for (int j = 0; j < 4; j++)
#pragma unroll
            for (int r = 0; r < 4; r++) acc[i][j][r] = 0.f;

    const int ntiles = K / TBK;

    // prologue: issue STAGES-1 tiles
#pragma unroll
    for (int t = 0; t < STAGES - 1; t++) {
        if (t < ntiles) {
            const float* Apn = Ap + (size_t)t * TBK * M;
            const float* Bpn = Bp + (size_t)t * TBK * N;
            cp_async16(&As[t][cr][cc],     Apn);
            cp_async16(&As[t][cr + 8][cc], Apn + a8);
            cp_async16(&Bs[t][cr][cc],     Bpn);
            cp_async16(&Bs[t][cr + 8][cc], Bpn + b8);
        }
        cp_commit();
    }

    int s = 0;
    for (int t = 0; t < ntiles; t++) {
        cp_wait<STAGES - 2>();
        __syncthreads();

        int tn = t + STAGES - 1;
        if (tn < ntiles) {
            int sw = (s + STAGES - 1) & (STAGES - 1);
            const float* Apn = Ap + (size_t)tn * TBK * M;
            const float* Bpn = Bp + (size_t)tn * TBK * N;
            cp_async16(&As[sw][cr][cc],     Apn);
            cp_async16(&As[sw][cr + 8][cc], Apn + a8);
            cp_async16(&Bs[sw][cr][cc],     Bpn);
            cp_async16(&Bs[sw][cr + 8][cc], Bpn + b8);
        }
        cp_commit();

#pragma unroll
        for (int kk = 0; kk < TBK; kk += 8) {
            uint32_t af[4][4], bf[4][2];
#pragma unroll
            for (int mt = 0; mt < 4; mt++) {
                int r0 = wm * 64 + mt * 16 + g;
                af[mt][0] = As[s][kk + th4][r0];
                af[mt][1] = As[s][kk + th4][r0 + 8];
                af[mt][2] = As[s][kk + th4 + 4][r0];
                af[mt][3] = As[s][kk + th4 + 4][r0 + 8];
            }
#pragma unroll
            for (int nt = 0; nt < 4; nt++) {
                int cb = wn * 32 + nt * 8 + g;
                bf[nt][0] = Bs[s][kk + th4][cb];
                bf[nt][1] = Bs[s][kk + th4 + 4][cb];
            }
#pragma unroll
            for (int mt = 0; mt < 4; mt++)
#pragma unroll
                for (int nt = 0; nt < 4; nt++)
                    mma_tf32(acc[mt][nt][0], acc[mt][nt][1], acc[mt][nt][2], acc[mt][nt][3],
                             af[mt][0], af[mt][1], af[mt][2], af[mt][3],
                             bf[nt][0], bf[nt][1]);
        }
        s = (s + 1) & (STAGES - 1);
    }

    // epilogue
#pragma unroll
    for (int mt = 0; mt < 4; mt++) {
        int row = m0 + wm * 64 + mt * 16 + g;
#pragma unroll
        for (int nt = 0; nt < 4; nt++) {
            int col = n0 + wn * 32 + nt * 8 + 2 * th4;
            float bc0 = bias_col ? bias_col[col]     : 0.f;
            float bc1 = bias_col ? bias_col[col + 1] : 0.f;
#pragma unroll
            for (int h = 0; h < 2; h++) {
                int r = row + h * 8;
                float br = bias_row ? bias_row[r] : 0.f;
                float2 o;
                o.x = acc[mt][nt][2 * h]     * alpha + br + bc0;
                o.y = acc[mt][nt][2 * h + 1] * alpha + br + bc1;
                if (residual) {
                    float2 rv = *(const float2*)(residual + (size_t)r * N + col);
                    o.x += rv.x; o.y += rv.y;
                }
                *(float2*)(C + (size_t)r * N + col) = o;
            }
        }
    }
}

// ---------------- column softmax on sT (softmax over slow dim) ---------------
__global__ void softmax_pass1()
{
    int b = blockIdx.z, rc = blockIdx.y, cb = blockIdx.x;
    int col = cb * 256 + threadIdx.x;
    const float* S = g_sT + (size_t)b * NN * NN + (size_t)rc * 512 * NN + col;
    float m = -1e30f, l = 0.f;
#pragma unroll 4
    for (int r = 0; r < 512; r++) {
        float v = S[(size_t)r * NN];
        if (v > m) { l = l * __expf(m - v) + 1.f; m = v; }
        else       { l += __expf(v - m); }
    }
    g_pm[((size_t)b * 8 + rc) * NN + col] = m;
    g_pl[((size_t)b * 8 + rc) * NN + col] = l;
}

__global__ void softmax_pass2()
{
    int b = blockIdx.z, rc = blockIdx.y, cb = blockIdx.x;
    int col = cb * 256 + threadIdx.x;
    float M = -1e30f;
#pragma unroll
    for (int c = 0; c < 8; c++) M = fmaxf(M, g_pm[((size_t)b * 8 + c) * NN + col]);
    float L = 0.f;
#pragma unroll
    for (int c = 0; c < 8; c++)
        L += g_pl[((size_t)b * 8 + c) * NN + col] * __expf(g_pm[((size_t)b * 8 + c) * NN + col] - M);
    float invL = 1.f / L;
    float* S = g_sT + (size_t)b * NN * NN + (size_t)rc * 512 * NN + col;
#pragma unroll 4
    for (int r = 0; r < 512; r++) {
        size_t off = (size_t)r * NN;
        S[off] = __expf(S[off] - M) * invL;
    }
}

// ---------------- launch -----------------------------------------------------
extern "C" void kernel_launch(void* const* d_in, const int* in_sizes, int n_in,
                              void* d_out, int out_size)
{
    const float* x     = (const float*)d_in[0];
    const float* gamma = (const float*)d_in[1];
    const float* beta  = (const float*)d_in[2];
    const float* wq    = (const float*)d_in[3];
    const float* bq    = (const float*)d_in[4];
    const float* wk    = (const float*)d_in[5];
    const float* bk    = (const float*)d_in[6];
    const float* wv    = (const float*)d_in[7];
    const float* bv    = (const float*)d_in[8];
    const float* wo    = (const float*)d_in[9];
    const float* bo    = (const float*)d_in[10];
    float* out = (float*)d_out;

    float *WqkT, *WvT, *WoT, *bqk, *hn, *qk, *v, *sT, *at;
    cudaGetSymbolAddress((void**)&WqkT, g_WqkT);
    cudaGetSymbolAddress((void**)&WvT,  g_WvT);
    cudaGetSymbolAddress((void**)&WoT,  g_WoT);
    cudaGetSymbolAddress((void**)&bqk,  g_bqk);
    cudaGetSymbolAddress((void**)&hn,   g_hn);
    cudaGetSymbolAddress((void**)&qk,   g_qk);
    cudaGetSymbolAddress((void**)&v,    g_v);
    cudaGetSymbolAddress((void**)&sT,   g_sT);
    cudaGetSymbolAddress((void**)&at,   g_at);

    static bool attr_set = false;
    if (!attr_set) {
        cudaFuncSetAttribute(tn_gemm_tc, cudaFuncAttributeMaxDynamicSharedMemorySize, SMEM_BYTES);
        attr_set = true;
    }

    prep_weights<<<(CC * 1024 + 512 + 255) / 256, 256>>>(wq, wk, wv, wo, bq, bk);
    gn_stats<<<BB * GG, 256>>>(x);
    gn_apply<<<(BB * CC * NN / 4) / 256, 256>>>(x, gamma, beta);

    // q,k in [d][n]:  bias over rows
    tn_gemm_tc<<<dim3(NN / TBN, 512 / TBM, BB), 256, SMEM_BYTES>>>(
        WqkT, hn, qk, 512, NN, CC,
        0, (size_t)CC * NN, (size_t)512 * NN,
        1.f, bqk, nullptr, nullptr);

    // v in [n][d]:  bias over cols
    tn_gemm_tc<<<dim3(CC / TBN, NN / TBM, BB), 256, SMEM_BYTES>>>(
        hn, WvT, v, NN, CC, CC,
        (size_t)CC * NN, 0, (size_t)NN * CC,
        1.f, nullptr, bv, nullptr);

    // sT[nk][nq] = (1/16) * k.q
    tn_gemm_tc<<<dim3(NN / TBN, NN / TBM, BB), 256, SMEM_BYTES>>>(
        qk + (size_t)CC * NN, qk, sT, NN, NN, CC,
        (size_t)512 * NN, (size_t)512 * NN, (size_t)NN * NN,
        0.0625f, nullptr, nullptr, nullptr);

    softmax_pass1<<<dim3(NN / 256, 8, BB), 256>>>();
    softmax_pass2<<<dim3(NN / 256, 8, BB), 256>>>();

    // attnT[c][nq] = sum_m v[m][c] * P[m][nq]
    tn_gemm_tc<<<dim3(NN / TBN, CC / TBM, BB), 256, SMEM_BYTES>>>(
        v, sT, at, CC, NN, NN,
        (size_t)NN * CC, (size_t)NN * NN, (size_t)CC * NN,
        1.f, nullptr, nullptr, nullptr);

    // out[d][n] = WoT^T x attnT + bo[d] + x   (written straight into d_out)
    tn_gemm_tc<<<dim3(NN / TBN, CC / TBM, BB), 256, SMEM_BYTES>>>(
        WoT, at, out, CC, NN, CC,
        0, (size_t)CC * NN, (size_t)CC * NN,
        1.f, bo, nullptr, x);
}

// round 6
// speedup vs baseline: 3.6356x; 1.3204x over previous
#include <cuda_runtime.h>
#include <cuda_bf16.h>
#include <cstdint>
#include <cstddef>

#define BB   4
#define CC   256
#define NN   4096
#define GG   32
#define CPG  8
#define EPSV 1e-5f

#define TBM 128
#define TBN 128
#define TBK 32
#define PAD 8
#define STAGES 3
#define NMT (NN / TBM)   // 32 m-tiles in scores GEMM

#define SMEM_WORDS_PER_STAGE (TBK * (TBM + PAD) + TBK * (TBN + PAD))
#define SMEM_BYTES (STAGES * SMEM_WORDS_PER_STAGE * 4)

// ---------------- scratch (device globals) ----------------------------------
__device__ float g_WqkT[CC * 512];
__device__ float g_WvT [CC * CC];
__device__ float g_WoT [CC * CC];
__device__ float g_bqk [512];
__device__ float g_hn  [BB * CC * NN];
__device__ float g_qk  [BB * 512 * NN];
__device__ float g_v   [(size_t)BB * NN * CC];
__device__ float g_sT  [(size_t)BB * NN * NN];   // holds expS after scores GEMM
__device__ float g_at  [BB * CC * NN];
__device__ float g_mean[BB * GG];
__device__ float g_rstd[BB * GG];
__device__ float g_ps  [(size_t)BB * NMT * NN];  // partial column sums
__device__ float g_invL[BB * NN];

// ---------------- helpers ----------------------------------------------------
__device__ __forceinline__ void mma_tf32(float& c0, float& c1, float& c2, float& c3,
                                         uint32_t a0, uint32_t a1, uint32_t a2, uint32_t a3,
                                         uint32_t b0, uint32_t b1)
{
    asm volatile(
        "mma.sync.aligned.m16n8k8.row.col.f32.tf32.tf32.f32 "
        "{%0,%1,%2,%3},{%4,%5,%6,%7},{%8,%9},{%0,%1,%2,%3};\n"
        : "+f"(c0), "+f"(c1), "+f"(c2), "+f"(c3)
        : "r"(a0), "r"(a1), "r"(a2), "r"(a3), "r"(b0), "r"(b1));
}

__device__ __forceinline__ void cp_async16(void* smem_dst, const void* gptr)
{
    uint32_t s = (uint32_t)__cvta_generic_to_shared(smem_dst);
    asm volatile("cp.async.cg.shared.global [%0], [%1], 16;\n" :: "r"(s), "l"(gptr));
}
__device__ __forceinline__ void cp_commit() { asm volatile("cp.async.commit_group;\n"); }
template <int Nw>
__device__ __forceinline__ void cp_wait() { asm volatile("cp.async.wait_group %0;\n" :: "n"(Nw)); }

// ---------------- weight prep ------------------------------------------------
__global__ void prep_weights(const float* __restrict__ wq, const float* __restrict__ wk,
                             const float* __restrict__ wv, const float* __restrict__ wo,
                             const float* __restrict__ bq, const float* __restrict__ bk)
{
    int i = blockIdx.x * blockDim.x + threadIdx.x;
    if (i < CC * 1024) {
        int c = i >> 10;
        int j = i & 1023;
        if (j < 256)       g_WqkT[c * 512 + j]        = wq[j * CC + c];
        else if (j < 512)  g_WqkT[c * 512 + j]        = wk[(j - 256) * CC + c];
        else if (j < 768)  g_WvT [c * CC + (j - 512)] = wv[(j - 512) * CC + c];
        else               g_WoT [c * CC + (j - 768)] = wo[(j - 768) * CC + c];
    } else {
        int j = i - CC * 1024;
        if (j < 512) g_bqk[j] = (j < 256) ? bq[j] : bk[j - 256];
    }
}

// ---------------- groupnorm --------------------------------------------------
__global__ void gn_stats(const float* __restrict__ x)
{
    int bg = blockIdx.x;
    const float* xs = x + (size_t)bg * (CPG * NN);
    float s = 0.f, s2 = 0.f;
    for (int i = threadIdx.x; i < CPG * NN; i += 256) {
        float v = xs[i];
        s += v; s2 += v * v;
    }
    __shared__ float rs[512];
    rs[threadIdx.x] = s; rs[256 + threadIdx.x] = s2;
    __syncthreads();
    for (int off = 128; off > 0; off >>= 1) {
        if (threadIdx.x < off) {
            rs[threadIdx.x]       += rs[threadIdx.x + off];
            rs[256 + threadIdx.x] += rs[256 + threadIdx.x + off];
        }
        __syncthreads();
    }
    if (threadIdx.x == 0) {
        float mean = rs[0] * (1.f / (CPG * NN));
        float var  = rs[256] * (1.f / (CPG * NN)) - mean * mean;
        g_mean[bg] = mean;
        g_rstd[bg] = rsqrtf(var + EPSV);
    }
}

__global__ void gn_apply(const float* __restrict__ x,
                         const float* __restrict__ gamma, const float* __restrict__ beta)
{
    int i = blockIdx.x * blockDim.x + threadIdx.x;
    size_t e = (size_t)i * 4;
    int c  = (int)((e >> 12) & 255);
    int bg = (int)(e >> 15);
    float mean = g_mean[bg], rstd = g_rstd[bg];
    float ga = gamma[c] * rstd;
    float be = beta[c] - mean * ga;
    float4 xv = *(const float4*)(x + e);
    float4 o;
    o.x = xv.x * ga + be; o.y = xv.y * ga + be;
    o.z = xv.z * ga + be; o.w = xv.w * ga + be;
    *(float4*)(g_hn + e) = o;
}

// ---------------- TF32 TC GEMM, 3-stage cp.async, TBK=32 ---------------------
// C[m][n] = sum_k A[k][m] * B[k][n], then per mode:
//  mode 0: o = acc*alpha + bias_row[m] + bias_col[n] (+resid)
//  mode 1: o = expf(acc*alpha); also writes per-(m-tile) column sums to colsum_out
//  mode 2: o = acc * colscale[bz*NN + n]
__global__ void __launch_bounds__(256, 2)
tn_gemm_tc(const float* __restrict__ A, const float* __restrict__ B, float* __restrict__ C,
           int M, int N, int K,
           size_t sA, size_t sB, size_t sC,
           float alpha,
           const float* __restrict__ bias_row, const float* __restrict__ bias_col,
           const float* __restrict__ residual,
           int mode, float* __restrict__ colsum_out, const float* __restrict__ colscale)
{
    int bz = blockIdx.z;
    A += (size_t)bz * sA;
    B += (size_t)bz * sB;
    C += (size_t)bz * sC;
    if (residual) residual += (size_t)bz * sC;

    const int m0 = blockIdx.y * TBM;
    const int n0 = blockIdx.x * TBN;

    extern __shared__ uint32_t smem[];
    typedef uint32_t AsT[TBK][TBM + PAD];
    typedef uint32_t BsT[TBK][TBN + PAD];
    AsT* As = (AsT*)smem;
    BsT* Bs = (BsT*)(smem + STAGES * TBK * (TBM + PAD));

    const int tid  = threadIdx.x;
    const int lane = tid & 31;
    const int wid  = tid >> 5;
    const int wm   = wid >> 2;
    const int wn   = wid & 3;
    const int g    = lane >> 2;
    const int th4  = lane & 3;

    const int cr = tid >> 5;          // 0..7, rows cr + j*8 (j=0..3)
    const int cc = (tid & 31) * 4;    // 0..124

    const float* Ap = A + (size_t)cr * M + m0 + cc;
    const float* Bp = B + (size_t)cr * N + n0 + cc;

    float acc[4][4][4];
#pragma unroll
    for (int i = 0; i < 4; i++)
#pragma unroll
        for (int j = 0; j < 4; j++)
#pragma unroll
            for (int r = 0; r < 4; r++) acc[i][j][r] = 0.f;

    const int T = K / TBK;

    // stage loader: k-chunk t -> slot st
    auto load_tile = [&](int st, int t) {
        const float* Apn = Ap + (size_t)t * TBK * M;
        const float* Bpn = Bp + (size_t)t * TBK * N;
#pragma unroll
        for (int j = 0; j < 4; j++) {
            cp_async16(&As[st][cr + j * 8][cc], Apn + (size_t)j * 8 * M);
            cp_async16(&Bs[st][cr + j * 8][cc], Bpn + (size_t)j * 8 * N);
        }
    };

    load_tile(0, 0); cp_commit();
    if (T > 1) { load_tile(1, 1); } cp_commit();

    for (int t = 0; t < T; t++) {
        cp_wait<1>();
        __syncthreads();

        if (t + 2 < T) load_tile((t + 2) % STAGES, t + 2);
        cp_commit();

        const int s = t % STAGES;
#pragma unroll
        for (int kk = 0; kk < TBK; kk += 8) {
            uint32_t af[4][4], bf[4][2];
#pragma unroll
            for (int mt = 0; mt < 4; mt++) {
                int r0 = wm * 64 + mt * 16 + g;
                af[mt][0] = As[s][kk + th4][r0];
                af[mt][1] = As[s][kk + th4][r0 + 8];
                af[mt][2] = As[s][kk + th4 + 4][r0];
                af[mt][3] = As[s][kk + th4 + 4][r0 + 8];
            }
#pragma unroll
            for (int nt = 0; nt < 4; nt++) {
                int cb = wn * 32 + nt * 8 + g;
                bf[nt][0] = Bs[s][kk + th4][cb];
                bf[nt][1] = Bs[s][kk + th4 + 4][cb];
            }
#pragma unroll
            for (int mt = 0; mt < 4; mt++)
#pragma unroll
                for (int nt = 0; nt < 4; nt++)
                    mma_tf32(acc[mt][nt][0], acc[mt][nt][1], acc[mt][nt][2], acc[mt][nt][3],
                             af[mt][0], af[mt][1], af[mt][2], af[mt][3],
                             bf[nt][0], bf[nt][1]);
        }
    }

    if (mode == 1) {
        // exp epilogue + per-tile column sums (no max subtraction; scores ~N(0,1))
        float lsum[8];
#pragma unroll
        for (int i = 0; i < 8; i++) lsum[i] = 0.f;

#pragma unroll
        for (int mt = 0; mt < 4; mt++) {
            int row = m0 + wm * 64 + mt * 16 + g;
#pragma unroll
            for (int nt = 0; nt < 4; nt++) {
                int col = n0 + wn * 32 + nt * 8 + 2 * th4;
#pragma unroll
                for (int h = 0; h < 2; h++) {
                    int r = row + h * 8;
                    float e0 = __expf(acc[mt][nt][2 * h]     * alpha);
                    float e1 = __expf(acc[mt][nt][2 * h + 1] * alpha);
                    lsum[nt * 2]     += e0;
                    lsum[nt * 2 + 1] += e1;
                    float2 o; o.x = e0; o.y = e1;
                    *(float2*)(C + (size_t)r * N + col) = o;
                }
            }
        }
        // reduce across g (lanes xor 4,8,16)
#pragma unroll
        for (int i = 0; i < 8; i++) {
            lsum[i] += __shfl_xor_sync(0xffffffffu, lsum[i], 4);
            lsum[i] += __shfl_xor_sync(0xffffffffu, lsum[i], 8);
            lsum[i] += __shfl_xor_sync(0xffffffffu, lsum[i], 16);
        }
        __shared__ float cs[2][TBN];
        if (g == 0) {
#pragma unroll
            for (int i = 0; i < 8; i++) {
                int cl = wn * 32 + (i >> 1) * 8 + 2 * th4 + (i & 1);
                cs[wm][cl] = lsum[i];
            }
        }
        __syncthreads();
        if (tid < TBN) {
            float sres = cs[0][tid] + cs[1][tid];
            colsum_out[((size_t)bz * NMT + blockIdx.y) * NN + n0 + tid] = sres;
        }
        return;
    }

    const float* csc = (mode == 2) ? (colscale + (size_t)bz * NN) : nullptr;
    float br[4], bc[4];
#pragma unroll
    for (int ii = 0; ii < 4; ii++) br[ii] = bias_row ? bias_row[m0 + wm * 64 + 0] : 0.f; // placeholder, set below
#pragma unroll
    for (int mt = 0; mt < 4; mt++) {
        int row = m0 + wm * 64 + mt * 16 + g;
#pragma unroll
        for (int nt = 0; nt < 4; nt++) {
            int col = n0 + wn * 32 + nt * 8 + 2 * th4;
            float bc0 = bias_col ? bias_col[col]     : 0.f;
            float bc1 = bias_col ? bias_col[col + 1] : 0.f;
            float sc0 = csc ? csc[col]     : 1.f;
            float sc1 = csc ? csc[col + 1] : 1.f;
#pragma unroll
            for (int h = 0; h < 2; h++) {
                int r = row + h * 8;
                float brv = bias_row ? bias_row[r] : 0.f;
                float2 o;
                o.x = (acc[mt][nt][2 * h]     * alpha + brv + bc0) * sc0;
                o.y = (acc[mt][nt][2 * h + 1] * alpha + brv + bc1) * sc1;
                if (residual) {
                    float2 rv = *(const float2*)(residual + (size_t)r * N + col);
                    o.x += rv.x; o.y += rv.y;
                }
                *(float2*)(C + (size_t)r * N + col) = o;
            }
        }
    }
    (void)br; (void)bc;
}

// ---------------- invL: reduce partial column sums ---------------------------
__global__ void invl_reduce()
{
    int idx = blockIdx.x * blockDim.x + threadIdx.x;   // b*NN + n
    int b = idx >> 12;
    int n = idx & (NN - 1);
    float s = 0.f;
#pragma unroll
    for (int t = 0; t < NMT; t++)
        s += g_ps[((size_t)b * NMT + t) * NN + n];
    g_invL[idx] = 1.f / s;
}

// ---------------- launch -----------------------------------------------------
extern "C" void kernel_launch(void* const* d_in, const int* in_sizes, int n_in,
                              void* d_out, int out_size)
{
    const float* x     = (const float*)d_in[0];
    const float* gamma = (const float*)d_in[1];
    const float* beta  = (const float*)d_in[2];
    const float* wq    = (const float*)d_in[3];
    const float* bq    = (const float*)d_in[4];
    const float* wk    = (const float*)d_in[5];
    const float* bk    = (const float*)d_in[6];
    const float* wv    = (const float*)d_in[7];
    const float* bv    = (const float*)d_in[8];
    const float* wo    = (const float*)d_in[9];
    const float* bo    = (const float*)d_in[10];
    float* out = (float*)d_out;

    float *WqkT, *WvT, *WoT, *bqk, *hn, *qk, *v, *sT, *at, *ps, *invL;
    cudaGetSymbolAddress((void**)&WqkT, g_WqkT);
    cudaGetSymbolAddress((void**)&WvT,  g_WvT);
    cudaGetSymbolAddress((void**)&WoT,  g_WoT);
    cudaGetSymbolAddress((void**)&bqk,  g_bqk);
    cudaGetSymbolAddress((void**)&hn,   g_hn);
    cudaGetSymbolAddress((void**)&qk,   g_qk);
    cudaGetSymbolAddress((void**)&v,    g_v);
    cudaGetSymbolAddress((void**)&sT,   g_sT);
    cudaGetSymbolAddress((void**)&at,   g_at);
    cudaGetSymbolAddress((void**)&ps,   g_ps);
    cudaGetSymbolAddress((void**)&invL, g_invL);

    static bool attr_set = false;
    if (!attr_set) {
        cudaFuncSetAttribute(tn_gemm_tc, cudaFuncAttributeMaxDynamicSharedMemorySize, SMEM_BYTES);
        attr_set = true;
    }

    prep_weights<<<(CC * 1024 + 512 + 255) / 256, 256>>>(wq, wk, wv, wo, bq, bk);
    gn_stats<<<BB * GG, 256>>>(x);
    gn_apply<<<(BB * CC * NN / 4) / 256, 256>>>(x, gamma, beta);

    // q,k in [d][n]:  bias over rows
    tn_gemm_tc<<<dim3(NN / TBN, 512 / TBM, BB), 256, SMEM_BYTES>>>(
        WqkT, hn, qk, 512, NN, CC,
        0, (size_t)CC * NN, (size_t)512 * NN,
        1.f, bqk, nullptr, nullptr, 0, nullptr, nullptr);

    // v in [n][d]:  bias over cols
    tn_gemm_tc<<<dim3(CC / TBN, NN / TBM, BB), 256, SMEM_BYTES>>>(
        hn, WvT, v, NN, CC, CC,
        (size_t)CC * NN, 0, (size_t)NN * CC,
        1.f, nullptr, bv, nullptr, 0, nullptr, nullptr);

    // expS[nk][nq] = exp(k.q / 16), plus per-tile column sums
    tn_gemm_tc<<<dim3(NN / TBN, NN / TBM, BB), 256, SMEM_BYTES>>>(
        qk + (size_t)CC * NN, qk, sT, NN, NN, CC,
        (size_t)512 * NN, (size_t)512 * NN, (size_t)NN * NN,
        0.0625f, nullptr, nullptr, nullptr, 1, ps, nullptr);

    invl_reduce<<<BB * NN / 256, 256>>>();

    // attnT[c][nq] = (sum_m v[m][c] * expS[m][nq]) * invL[nq]
    tn_gemm_tc<<<dim3(NN / TBN, CC / TBM, BB), 256, SMEM_BYTES>>>(
        v, sT, at, CC, NN, NN,
        (size_t)NN * CC, (size_t)NN * NN, (size_t)CC * NN,
        1.f, nullptr, nullptr, nullptr, 2, nullptr, invL);

    // out[d][n] = WoT^T x attnT + bo[d] + x
    tn_gemm_tc<<<dim3(NN / TBN, CC / TBM, BB), 256, SMEM_BYTES>>>(
        WoT, at, out, CC, NN, CC,
        0, (size_t)CC * NN, (size_t)CC * NN,
        1.f, bo, nullptr, x, 0, nullptr, nullptr);
}

// round 7
// speedup vs baseline: 6.1151x; 1.6820x over previous
#include <cuda_runtime.h>
#include <cuda_fp16.h>
#include <cstdint>
#include <cstddef>

#define BB   4
#define CC   256
#define NN   4096
#define GG   32
#define CPG  8
#define EPSV 1e-5f

#define TBM 128
#define TBN 128
#define TBK 32            // halves per k-chunk (2 x k16 MMA steps)
#define SKH 40            // smem row stride in halves (80B) -> LDSM conflict-free
#define STAGES 4
#define TILE_B (TBM * SKH * 2)        // 10240 bytes per tile
#define STAGE_B (2 * TILE_B)          // 20480
#define SMEM_BYTES (STAGES * STAGE_B) // 81920
#define NMT (NN / TBN)                // 32 n-tiles (scores partial sums)

// ---------------- scratch (device globals) ----------------------------------
__device__ __half g_wqkh[512 * CC];              // rows 0-255: wq/4, 256-511: wk/4
__device__ __half g_wvh [CC * CC];
__device__ __half g_woh [CC * CC];
__device__ float  g_bqk [512];                   // bq/4, bk/4
__device__ __half g_hn  [(size_t)BB * NN * CC];  // [b][n][c]
__device__ __half g_qkh [(size_t)BB * NN * 512]; // [b][n][512]
__device__ __half g_v   [(size_t)BB * CC * NN];  // [b][c][n]
__device__ __half g_eS  [(size_t)BB * NN * NN];  // expS [b][nq][nk]
__device__ __half g_at  [(size_t)BB * NN * CC];  // attn [b][nq][c]
__device__ float  g_mean[BB * GG];
__device__ float  g_rstd[BB * GG];
__device__ float  g_ps  [(size_t)BB * NMT * NN]; // partial row sums
__device__ float  g_invL[BB * NN];

// ---------------- helpers ----------------------------------------------------
__device__ __forceinline__ void mma_f16(float* c, const uint32_t* a, uint32_t b0, uint32_t b1)
{
    asm volatile(
        "mma.sync.aligned.m16n8k16.row.col.f32.f16.f16.f32 "
        "{%0,%1,%2,%3},{%4,%5,%6,%7},{%8,%9},{%0,%1,%2,%3};\n"
        : "+f"(c[0]), "+f"(c[1]), "+f"(c[2]), "+f"(c[3])
        : "r"(a[0]), "r"(a[1]), "r"(a[2]), "r"(a[3]), "r"(b0), "r"(b1));
}
__device__ __forceinline__ void ldsm_x4(uint32_t* r, uint32_t addr)
{
    asm volatile("ldmatrix.sync.aligned.m8n8.x4.shared.b16 {%0,%1,%2,%3}, [%4];"
                 : "=r"(r[0]), "=r"(r[1]), "=r"(r[2]), "=r"(r[3]) : "r"(addr));
}
__device__ __forceinline__ void cp_async16(void* smem_dst, const void* gptr)
{
    uint32_t s = (uint32_t)__cvta_generic_to_shared(smem_dst);
    asm volatile("cp.async.cg.shared.global [%0], [%1], 16;\n" :: "r"(s), "l"(gptr));
}
__device__ __forceinline__ void cp_commit() { asm volatile("cp.async.commit_group;\n"); }
template <int Nw>
__device__ __forceinline__ void cp_wait() { asm volatile("cp.async.wait_group %0;\n" :: "n"(Nw)); }

// ---------------- prep: convert weights to half ------------------------------
__global__ void prep_weights(const float* __restrict__ wq, const float* __restrict__ wk,
                             const float* __restrict__ wv, const float* __restrict__ wo,
                             const float* __restrict__ bq, const float* __restrict__ bk)
{
    int i = blockIdx.x * blockDim.x + threadIdx.x;
    if (i < 131072) {                         // wqk (512x256), scaled 1/4
        int r = i >> 8;
        float v = (r < 256) ? wq[i] : wk[i - 65536];
        g_wqkh[i] = __float2half(v * 0.25f);
    } else if (i < 196608) {
        g_wvh[i - 131072] = __float2half(wv[i - 131072]);
    } else if (i < 262144) {
        g_woh[i - 196608] = __float2half(wo[i - 196608]);
    } else if (i < 262656) {
        int j = i - 262144;
        g_bqk[j] = ((j < 256) ? bq[j] : bk[j - 256]) * 0.25f;
    }
}

// ---------------- groupnorm --------------------------------------------------
__global__ void gn_stats(const float* __restrict__ x)
{
    int bg = blockIdx.x;
    const float* xs = x + (size_t)bg * (CPG * NN);
    float s = 0.f, s2 = 0.f;
    for (int i = threadIdx.x; i < CPG * NN; i += 256) {
        float v = xs[i];
        s += v; s2 += v * v;
    }
    __shared__ float rs[512];
    rs[threadIdx.x] = s; rs[256 + threadIdx.x] = s2;
    __syncthreads();
    for (int off = 128; off > 0; off >>= 1) {
        if (threadIdx.x < off) {
            rs[threadIdx.x]       += rs[threadIdx.x + off];
            rs[256 + threadIdx.x] += rs[256 + threadIdx.x + off];
        }
        __syncthreads();
    }
    if (threadIdx.x == 0) {
        float mean = rs[0] * (1.f / (CPG * NN));
        float var  = rs[256] * (1.f / (CPG * NN)) - mean * mean;
        g_mean[bg] = mean;
        g_rstd[bg] = rsqrtf(var + EPSV);
    }
}

// x[b][c][n] -> hn[b][n][c] (half). block (32,8), grid (NN/32, CC/32, BB)
__global__ void gn_transpose(const float* __restrict__ x,
                             const float* __restrict__ gamma, const float* __restrict__ beta)
{
    __shared__ float tile[32][33];
    int b = blockIdx.z;
    int n0 = blockIdx.x * 32, c0 = blockIdx.y * 32;
    int tx = threadIdx.x, ty = threadIdx.y;
    const float* xb = x + (size_t)b * CC * NN;
#pragma unroll
    for (int j = 0; j < 4; j++) {
        int c = c0 + ty + j * 8;
        float mean = g_mean[b * GG + (c >> 3)];
        float rstd = g_rstd[b * GG + (c >> 3)];
        float ga = gamma[c] * rstd;
        float be = beta[c] - mean * ga;
        tile[ty + j * 8][tx] = xb[(size_t)c * NN + n0 + tx] * ga + be;
    }
    __syncthreads();
    __half* hb = g_hn + (size_t)b * NN * CC;
#pragma unroll
    for (int j = 0; j < 4; j++) {
        int n = n0 + ty + j * 8;
        hb[(size_t)n * CC + c0 + tx] = __float2half(tile[tx][ty + j * 8]);
    }
}

// ---------------- fp16 tensor-core GEMM, row-major K-contiguous --------------
// C[m][n] = sum_k A[m][k] * B[n][k]
// mode 0: half out, + bias_row[m] + bias_col[n] (fp32 biases)
// mode 1: half out = exp(acc); per-(n-tile) row sums -> psum
// mode 2: half out = acc * rowscale[b*M + m]
// mode 3: fp32 out = acc + bias_row[m] + residual
__global__ void __launch_bounds__(256, 2)
hgemm(const __half* __restrict__ A, int ldA, size_t sA,
      const __half* __restrict__ B, int ldB, size_t sB,
      void* __restrict__ Cv, int ldC, size_t sC,
      int M, int K,
      const float* __restrict__ bias_row, const float* __restrict__ bias_col,
      const float* __restrict__ residual, const float* __restrict__ rowscale,
      float* __restrict__ psum, int mode)
{
    const int b  = blockIdx.z;
    const int m0 = blockIdx.y * TBM;
    const int n0 = blockIdx.x * TBN;

    extern __shared__ char smem[];

    const int tid  = threadIdx.x;
    const int lane = tid & 31;
    const int wid  = tid >> 5;
    const int wm   = wid >> 2;        // m offset wm*64
    const int wn   = wid & 3;         // n offset wn*32
    const int g    = lane >> 2;
    const int th4  = lane & 3;
    const int mi   = lane >> 3;       // ldmatrix matrix idx
    const int ri   = lane & 7;        // ldmatrix row idx

    const __half* Ap = A + (size_t)b * sA + (size_t)m0 * ldA;
    const __half* Bp = B + (size_t)b * sB + (size_t)n0 * ldB;

    const uint32_t su = (uint32_t)__cvta_generic_to_shared(smem);

    float acc[4][4][4];
#pragma unroll
    for (int i = 0; i < 4; i++)
#pragma unroll
        for (int j = 0; j < 4; j++)
#pragma unroll
            for (int r = 0; r < 4; r++) acc[i][j][r] = 0.f;

    const int T = K / TBK;
    const int crow = tid >> 2;        // 0..63? no: tid>>2 -> 0..63 (two j steps cover 128)
    const int c4   = tid & 3;         // 16B slot within row

    auto load_tile = [&](int st, int t) {
        char* sa = smem + st * STAGE_B;
        char* sb = sa + TILE_B;
        const __half* Ag = Ap + (size_t)t * TBK;
        const __half* Bg = Bp + (size_t)t * TBK;
#pragma unroll
        for (int j = 0; j < 2; j++) {
            int row = crow + j * 64;
            cp_async16(sa + row * (SKH * 2) + c4 * 16, Ag + (size_t)row * ldA + c4 * 8);
            cp_async16(sb + row * (SKH * 2) + c4 * 16, Bg + (size_t)row * ldB + c4 * 8);
        }
    };

#pragma unroll
    for (int t = 0; t < STAGES - 1; t++) {
        if (t < T) load_tile(t, t);
        cp_commit();
    }

    for (int t = 0; t < T; t++) {
        cp_wait<STAGES - 2>();
        __syncthreads();

        int tl = t + STAGES - 1;
        if (tl < T) load_tile(tl % STAGES, tl);
        cp_commit();

        const int slot = t % STAGES;
        const uint32_t a_base = su + slot * STAGE_B;
        const uint32_t b_base = a_base + TILE_B;

#pragma unroll
        for (int kk = 0; kk < TBK; kk += 16) {
            uint32_t av[4][4];
#pragma unroll
            for (int mt = 0; mt < 4; mt++) {
                int row = wm * 64 + mt * 16 + ((mi & 1) << 3) + ri;
                int col = kk + ((mi & 2) << 2);
                ldsm_x4(av[mt], a_base + (row * SKH + col) * 2);
            }
            uint32_t bv[2][4];
#pragma unroll
            for (int p = 0; p < 2; p++) {
                int row = wn * 32 + p * 16 + ((mi >> 1) << 3) + ri;
                int col = kk + ((mi & 1) << 3);
                ldsm_x4(bv[p], b_base + (row * SKH + col) * 2);
            }
#pragma unroll
            for (int mt = 0; mt < 4; mt++)
#pragma unroll
                for (int nt = 0; nt < 4; nt++)
                    mma_f16(acc[mt][nt], av[mt], bv[nt >> 1][(nt & 1) * 2], bv[nt >> 1][(nt & 1) * 2 + 1]);
        }
    }

    // ---------------- epilogues ----------------
    if (mode == 1) {
        __half* C = (__half*)Cv + (size_t)b * sC;
        float rsum[8];
#pragma unroll
        for (int i = 0; i < 8; i++) rsum[i] = 0.f;
#pragma unroll
        for (int mt = 0; mt < 4; mt++) {
#pragma unroll
            for (int nt = 0; nt < 4; nt++) {
                int col = n0 + wn * 32 + nt * 8 + 2 * th4;
#pragma unroll
                for (int h = 0; h < 2; h++) {
                    int row = m0 + wm * 64 + mt * 16 + g + 8 * h;
                    float e0 = __expf(acc[mt][nt][2 * h]);
                    float e1 = __expf(acc[mt][nt][2 * h + 1]);
                    rsum[mt * 2 + h] += e0 + e1;
                    *(__half2*)(C + (size_t)row * ldC + col) = __floats2half2_rn(e0, e1);
                }
            }
        }
#pragma unroll
        for (int i = 0; i < 8; i++) {
            rsum[i] += __shfl_xor_sync(0xffffffffu, rsum[i], 1);
            rsum[i] += __shfl_xor_sync(0xffffffffu, rsum[i], 2);
        }
        __syncthreads();                       // tiles no longer needed; reuse smem
        float* rsm = (float*)smem;             // [4][128]
        if (th4 == 0) {
#pragma unroll
            for (int mt = 0; mt < 4; mt++)
#pragma unroll
                for (int h = 0; h < 2; h++)
                    rsm[wn * 128 + wm * 64 + mt * 16 + g + 8 * h] = rsum[mt * 2 + h];
        }
        __syncthreads();
        if (tid < 128) {
            float tot = rsm[tid] + rsm[128 + tid] + rsm[256 + tid] + rsm[384 + tid];
            psum[((size_t)b * gridDim.x + blockIdx.x) * M + m0 + tid] = tot;
        }
        return;
    }

    if (mode == 3) {
        float* C = (float*)Cv + (size_t)b * sC;
        const float* R = residual + (size_t)b * sC;
#pragma unroll
        for (int mt = 0; mt < 4; mt++) {
#pragma unroll
            for (int nt = 0; nt < 4; nt++) {
                int col = n0 + wn * 32 + nt * 8 + 2 * th4;
#pragma unroll
                for (int h = 0; h < 2; h++) {
                    int row = m0 + wm * 64 + mt * 16 + g + 8 * h;
                    float br = bias_row[row];
                    float2 rv = *(const float2*)(R + (size_t)row * ldC + col);
                    float2 o;
                    o.x = acc[mt][nt][2 * h]     + br + rv.x;
                    o.y = acc[mt][nt][2 * h + 1] + br + rv.y;
                    *(float2*)(C + (size_t)row * ldC + col) = o;
                }
            }
        }
        return;
    }

    __half* C = (__half*)Cv + (size_t)b * sC;
    const float* rsc = (mode == 2) ? (rowscale + (size_t)b * M) : nullptr;
#pragma unroll
    for (int mt = 0; mt < 4; mt++) {
#pragma unroll
        for (int nt = 0; nt < 4; nt++) {
            int col = n0 + wn * 32 + nt * 8 + 2 * th4;
            float bc0 = bias_col ? bias_col[col]     : 0.f;
            float bc1 = bias_col ? bias_col[col + 1] : 0.f;
#pragma unroll
            for (int h = 0; h < 2; h++) {
                int row = m0 + wm * 64 + mt * 16 + g + 8 * h;
                float o0 = acc[mt][nt][2 * h];
                float o1 = acc[mt][nt][2 * h + 1];
                if (mode == 2) {
                    float sc = rsc[row];
                    o0 *= sc; o1 *= sc;
                } else {
                    float br = bias_row ? bias_row[row] : 0.f;
                    o0 += br + bc0; o1 += br + bc1;
                }
                *(__half2*)(C + (size_t)row * ldC + col) = __floats2half2_rn(o0, o1);
            }
        }
    }
}

// ---------------- invL: reduce partial row sums ------------------------------
__global__ void invl_reduce()
{
    int idx = blockIdx.x * blockDim.x + threadIdx.x;   // b*NN + nq
    int b = idx >> 12;
    int n = idx & (NN - 1);
    float s = 0.f;
#pragma unroll
    for (int t = 0; t < NMT; t++)
        s += g_ps[((size_t)b * NMT + t) * NN + n];
    g_invL[idx] = 1.f / s;
}

// ---------------- launch -----------------------------------------------------
extern "C" void kernel_launch(void* const* d_in, const int* in_sizes, int n_in,
                              void* d_out, int out_size)
{
    const float* x     = (const float*)d_in[0];
    const float* gamma = (const float*)d_in[1];
    const float* beta  = (const float*)d_in[2];
    const float* wq    = (const float*)d_in[3];
    const float* bq    = (const float*)d_in[4];
    const float* wk    = (const float*)d_in[5];
    const float* bk    = (const float*)d_in[6];
    const float* wv    = (const float*)d_in[7];
    const float* bv    = (const float*)d_in[8];
    const float* wo    = (const float*)d_in[9];
    const float* bo    = (const float*)d_in[10];
    float* out = (float*)d_out;

    __half *wqkh, *wvh, *woh, *hn, *qkh, *v, *eS, *at;
    float *bqk, *ps, *invL;
    cudaGetSymbolAddress((void**)&wqkh, g_wqkh);
    cudaGetSymbolAddress((void**)&wvh,  g_wvh);
    cudaGetSymbolAddress((void**)&woh,  g_woh);
    cudaGetSymbolAddress((void**)&bqk,  g_bqk);
    cudaGetSymbolAddress((void**)&hn,   g_hn);
    cudaGetSymbolAddress((void**)&qkh,  g_qkh);
    cudaGetSymbolAddress((void**)&v,    g_v);
    cudaGetSymbolAddress((void**)&eS,   g_eS);
    cudaGetSymbolAddress((void**)&at,   g_at);
    cudaGetSymbolAddress((void**)&ps,   g_ps);
    cudaGetSymbolAddress((void**)&invL, g_invL);

    static bool attr_set = false;
    if (!attr_set) {
        cudaFuncSetAttribute(hgemm, cudaFuncAttributeMaxDynamicSharedMemorySize, SMEM_BYTES);
        attr_set = true;
    }

    prep_weights<<<(262656 + 255) / 256, 256>>>(wq, wk, wv, wo, bq, bk);
    gn_stats<<<BB * GG, 256>>>(x);
    gn_transpose<<<dim3(NN / 32, CC / 32, BB), dim3(32, 8)>>>(x, gamma, beta);

    // qk[n][512] = hn[n][c] x wqk[d][c]^T + bqk   (q,k pre-scaled by 1/4)
    hgemm<<<dim3(512 / TBN, NN / TBM, BB), 256, SMEM_BYTES>>>(
        hn, CC, (size_t)NN * CC, wqkh, CC, 0,
        qkh, 512, (size_t)NN * 512, NN, CC,
        nullptr, bqk, nullptr, nullptr, nullptr, 0);

    // v[c][n] = wv[c][k] x hn[n][k]^T + bv[c]
    hgemm<<<dim3(NN / TBN, CC / TBM, BB), 256, SMEM_BYTES>>>(
        wvh, CC, 0, hn, CC, (size_t)NN * CC,
        v, NN, (size_t)CC * NN, CC, CC,
        bv, nullptr, nullptr, nullptr, nullptr, 0);

    // expS[nq][nk] = exp(q . k), with per-n-tile row sums
    hgemm<<<dim3(NN / TBN, NN / TBM, BB), 256, SMEM_BYTES>>>(
        qkh, 512, (size_t)NN * 512, qkh + 256, 512, (size_t)NN * 512,
        eS, NN, (size_t)NN * NN, NN, CC,
        nullptr, nullptr, nullptr, nullptr, ps, 1);

    invl_reduce<<<BB * NN / 256, 256>>>();

    // attn[nq][c] = (expS[nq][nk] x v[c][nk]^T) * invL[nq]
    hgemm<<<dim3(CC / TBN, NN / TBM, BB), 256, SMEM_BYTES>>>(
        eS, NN, (size_t)NN * NN, v, NN, (size_t)CC * NN,
        at, CC, (size_t)NN * CC, NN, NN,
        nullptr, nullptr, nullptr, invL, nullptr, 2);

    // out[c][n] = wo[c][k] x attn[n][k]^T + bo[c] + x[c][n]   (fp32)
    hgemm<<<dim3(NN / TBN, CC / TBM, BB), 256, SMEM_BYTES>>>(
        woh, CC, 0, at, CC, (size_t)NN * CC,
        out, NN, (size_t)CC * NN, CC, CC,
        bo, nullptr, x, nullptr, nullptr, 3);
}